// round 1
// baseline (speedup 1.0000x reference)
#include <cuda_runtime.h>
#include <cstdint>
#include <cstddef>

// Problem constants
#define EXPERTS 8
#define TOK     2048
#define DMODEL  1024
#define HID     4096

// Intermediate hidden activations [E, T, H] fp32 = 256MB (static device scratch;
// no allocation allowed in kernel_launch)
__device__ float g_hidden[(size_t)EXPERTS * TOK * HID];

// Tiling
#define BM 128
#define BN 128
#define BK 16
#define PADA 4   // As[BM][BK+PADA]: frag bank = (36*grp + qid) % 32 = 4*grp+qid -> conflict-free
#define PADB 8   // Bs[BK][BN+PADB]: frag bank = (136*qid + grp) % 32 = 8*qid+grp -> conflict-free

__device__ __forceinline__ uint32_t f2tf32(float f) {
    uint32_t u;
    asm("cvt.rna.tf32.f32 %0, %1;" : "=r"(u) : "f"(f));
    return u;
}

__device__ __forceinline__ void cp_async16(void* smem_dst, const void* gmem_src) {
    uint32_t s = (uint32_t)__cvta_generic_to_shared(smem_dst);
    asm volatile("cp.async.cg.shared.global [%0], [%1], 16;" :: "r"(s), "l"(gmem_src));
}

// C[M,N] = A[M,K] (row-major) * B[K,N] (row-major) + bias[N], optional ReLU.
// Batched over blockIdx.z. M,N divisible by 128; K divisible by 16 (all hold here).
template <bool RELU>
__global__ __launch_bounds__(256, 2)
void ffn_gemm(const float* __restrict__ A, const float* __restrict__ B,
              const float* __restrict__ bias, float* __restrict__ C,
              int M, int N, int K)
{
    __shared__ float As[2][BM][BK + PADA];
    __shared__ float Bs[2][BK][BN + PADB];

    const int e = blockIdx.z;
    const float* Ae = A + (size_t)e * M * K;
    const float* Be = B + (size_t)e * K * N;
    const float* be = bias + (size_t)e * N;
    float*       Ce = C + (size_t)e * M * N;

    const int bm = blockIdx.y * BM;
    const int bn = blockIdx.x * BN;

    const int tid  = threadIdx.x;
    const int warp = tid >> 5;
    const int lane = tid & 31;
    const int wm   = (warp >> 2) * 64;   // warp tile: 64 rows
    const int wn   = (warp & 3) * 32;    // warp tile: 32 cols
    const int grp  = lane >> 2;          // 0..7
    const int qid  = lane & 3;           // 0..3

    float c[4][4][4];
    #pragma unroll
    for (int i = 0; i < 4; i++)
        #pragma unroll
        for (int j = 0; j < 4; j++)
            #pragma unroll
            for (int r = 0; r < 4; r++) c[i][j][r] = 0.f;

    const int nk = K / BK;

    // Async loader: A tile 128x16 (512 float4), B tile 16x128 (512 float4); 2 each/thread.
    auto issue = [&](int t, int s) {
        const int k0 = t * BK;
        #pragma unroll
        for (int i = 0; i < 2; i++) {
            int f = tid + i * 256;
            int ar = f >> 2, ac4 = (f & 3) << 2;          // A: row, col4
            cp_async16(&As[s][ar][ac4], Ae + (size_t)(bm + ar) * K + k0 + ac4);
            int br = f >> 5, bc4 = (f & 31) << 2;          // B: row, col4
            cp_async16(&Bs[s][br][bc4], Be + (size_t)(k0 + br) * N + bn + bc4);
        }
        asm volatile("cp.async.commit_group;" ::: "memory");
    };

    issue(0, 0);

    for (int t = 0; t < nk; t++) {
        asm volatile("cp.async.wait_group 0;" ::: "memory");
        __syncthreads();
        if (t + 1 < nk) issue(t + 1, (t + 1) & 1);
        const int s = t & 1;

        #pragma unroll
        for (int kk = 0; kk < BK; kk += 8) {
            uint32_t a[4][4], b[4][2];
            #pragma unroll
            for (int i = 0; i < 4; i++) {
                int rm = wm + i * 16;
                a[i][0] = f2tf32(As[s][rm + grp    ][kk + qid    ]);
                a[i][1] = f2tf32(As[s][rm + grp + 8][kk + qid    ]);
                a[i][2] = f2tf32(As[s][rm + grp    ][kk + qid + 4]);
                a[i][3] = f2tf32(As[s][rm + grp + 8][kk + qid + 4]);
            }
            #pragma unroll
            for (int j = 0; j < 4; j++) {
                int cn = wn + j * 8;
                b[j][0] = f2tf32(Bs[s][kk + qid    ][cn + grp]);
                b[j][1] = f2tf32(Bs[s][kk + qid + 4][cn + grp]);
            }
            #pragma unroll
            for (int i = 0; i < 4; i++)
                #pragma unroll
                for (int j = 0; j < 4; j++) {
                    asm volatile(
                        "mma.sync.aligned.m16n8k8.row.col.f32.tf32.tf32.f32 "
                        "{%0,%1,%2,%3}, {%4,%5,%6,%7}, {%8,%9}, {%0,%1,%2,%3};"
                        : "+f"(c[i][j][0]), "+f"(c[i][j][1]),
                          "+f"(c[i][j][2]), "+f"(c[i][j][3])
                        : "r"(a[i][0]), "r"(a[i][1]), "r"(a[i][2]), "r"(a[i][3]),
                          "r"(b[j][0]), "r"(b[j][1]));
                }
        }
        __syncthreads();
    }

    // Epilogue: bias + optional ReLU, float2 stores (cols 2*qid, 2*qid+1 contiguous)
    #pragma unroll
    for (int i = 0; i < 4; i++) {
        int r0 = bm + wm + i * 16 + grp;
        #pragma unroll
        for (int j = 0; j < 4; j++) {
            int cn = bn + wn + j * 8 + 2 * qid;
            float bv0 = be[cn], bv1 = be[cn + 1];
            float v0 = c[i][j][0] + bv0;
            float v1 = c[i][j][1] + bv1;
            float v2 = c[i][j][2] + bv0;
            float v3 = c[i][j][3] + bv1;
            if (RELU) {
                v0 = fmaxf(v0, 0.f); v1 = fmaxf(v1, 0.f);
                v2 = fmaxf(v2, 0.f); v3 = fmaxf(v3, 0.f);
            }
            *(float2*)&Ce[(size_t)r0 * N + cn]       = make_float2(v0, v1);
            *(float2*)&Ce[(size_t)(r0 + 8) * N + cn] = make_float2(v2, v3);
        }
    }
}

extern "C" void kernel_launch(void* const* d_in, const int* in_sizes, int n_in,
                              void* d_out, int out_size)
{
    const float* x  = (const float*)d_in[0];   // [E, T, D]
    const float* w1 = (const float*)d_in[1];   // [E, D, H]
    const float* b1 = (const float*)d_in[2];   // [E, 1, H]
    const float* w2 = (const float*)d_in[3];   // [E, H, D]
    const float* b2 = (const float*)d_in[4];   // [E, 1, D]
    float* out = (float*)d_out;                // [E, T, D]

    float* hid = nullptr;
    cudaGetSymbolAddress((void**)&hid, g_hidden);

    dim3 blk(256);
    dim3 g1(HID / BN, TOK / BM, EXPERTS);      // (32, 16, 8)
    ffn_gemm<true><<<g1, blk>>>(x, w1, b1, hid, TOK, HID, DMODEL);

    dim3 g2(DMODEL / BN, TOK / BM, EXPERTS);   // (8, 16, 8)
    ffn_gemm<false><<<g2, blk>>>(hid, w2, b2, out, TOK, DMODEL, HID);
}